// round 1
// baseline (speedup 1.0000x reference)
#include <cuda_runtime.h>
#include <cstdint>

#define DIMC  1024
#define NHEAD 16
#define HDIM  64
#define BATCH 2
#define SEQ   2048
#define MROWS (BATCH * SEQ)   // 4096

// Scratch (allocation-free rule: __device__ globals)
__device__ float g_qh[BATCH * NHEAD * SEQ * HDIM];  // [bh][n][d]
__device__ float g_kh[BATCH * NHEAD * SEQ * HDIM];
__device__ float g_vh[BATCH * NHEAD * SEQ * HDIM];
__device__ float g_x [MROWS * DIMC];                // [b*n][c] attention output pre-proj

// ---------------------------------------------------------------------------
// NT GEMM: out[m,n] = sum_k A[m,k] * W[n,k] (+bias). 128x128x16 tile, 8x8/thread.
// mode 0: plain row-major MxDIMC output (+bias)
// mode 1: head-scatter into [bh][n_seq][d] layout (for qh/kh/vh)
// ---------------------------------------------------------------------------
__global__ __launch_bounds__(256)
void gemm_nt(const float* __restrict__ A, const float* __restrict__ W,
             const float* __restrict__ bias, float* __restrict__ out, int mode)
{
    const int K = DIMC;
    __shared__ float sA[16 * 128];
    __shared__ float sB[16 * 128];

    const int tid = threadIdx.x;
    const int m0 = blockIdx.y * 128;
    const int n0 = blockIdx.x * 128;
    const int ty = tid >> 4;
    const int tx = tid & 15;

    float acc[8][8];
#pragma unroll
    for (int i = 0; i < 8; ++i)
#pragma unroll
        for (int j = 0; j < 8; ++j) acc[i][j] = 0.0f;

    for (int k0 = 0; k0 < K; k0 += 16) {
#pragma unroll
        for (int l = 0; l < 2; ++l) {
            int id  = tid + l * 256;        // 0..511
            int row = id >> 2;              // 0..127
            int kc  = (id & 3) << 2;        // 0,4,8,12
            float4 va = *(const float4*)(A + (size_t)(m0 + row) * K + k0 + kc);
            sA[(kc + 0) * 128 + row] = va.x;
            sA[(kc + 1) * 128 + row] = va.y;
            sA[(kc + 2) * 128 + row] = va.z;
            sA[(kc + 3) * 128 + row] = va.w;
            float4 vb = *(const float4*)(W + (size_t)(n0 + row) * K + k0 + kc);
            sB[(kc + 0) * 128 + row] = vb.x;
            sB[(kc + 1) * 128 + row] = vb.y;
            sB[(kc + 2) * 128 + row] = vb.z;
            sB[(kc + 3) * 128 + row] = vb.w;
        }
        __syncthreads();

#pragma unroll
        for (int kk = 0; kk < 16; ++kk) {
            float4 a0 = *(const float4*)&sA[kk * 128 + ty * 8];
            float4 a1 = *(const float4*)&sA[kk * 128 + ty * 8 + 4];
            float4 b0 = *(const float4*)&sB[kk * 128 + tx * 8];
            float4 b1 = *(const float4*)&sB[kk * 128 + tx * 8 + 4];
            float a[8] = {a0.x, a0.y, a0.z, a0.w, a1.x, a1.y, a1.z, a1.w};
            float b[8] = {b0.x, b0.y, b0.z, b0.w, b1.x, b1.y, b1.z, b1.w};
#pragma unroll
            for (int i = 0; i < 8; ++i)
#pragma unroll
                for (int j = 0; j < 8; ++j)
                    acc[i][j] = fmaf(a[i], b[j], acc[i][j]);
        }
        __syncthreads();
    }

    if (mode == 0) {
#pragma unroll
        for (int i = 0; i < 8; ++i) {
            int m = m0 + ty * 8 + i;
            float* op = out + (size_t)m * DIMC + n0 + tx * 8;
#pragma unroll
            for (int j4 = 0; j4 < 8; j4 += 4) {
                float4 bb = *(const float4*)(bias + n0 + tx * 8 + j4);
                float4 v;
                v.x = acc[i][j4 + 0] + bb.x;
                v.y = acc[i][j4 + 1] + bb.y;
                v.z = acc[i][j4 + 2] + bb.z;
                v.w = acc[i][j4 + 3] + bb.w;
                *(float4*)(op + j4) = v;
            }
        }
    } else {
        // scatter to [(b*16+h)][ns][d]
#pragma unroll
        for (int i = 0; i < 8; ++i) {
            int m  = m0 + ty * 8 + i;
            int b  = m >> 11;
            int ns = m & 2047;
#pragma unroll
            for (int j4 = 0; j4 < 8; j4 += 4) {
                int n = n0 + tx * 8 + j4;
                int h = n >> 6;
                int d = n & 63;
                float4 v = make_float4(acc[i][j4], acc[i][j4 + 1], acc[i][j4 + 2], acc[i][j4 + 3]);
                *(float4*)(out + (((size_t)(b * NHEAD + h) * SEQ + ns) * HDIM + d)) = v;
            }
        }
    }
}

// ---------------------------------------------------------------------------
// Fused attention for one (bh, 64-row query tile).
// Two passes over key tiles: pass1 = online (rowmax, rowsumexp); pass2 =
// recompute S, write normalized attn to gmem, accumulate O += P@V.
// Softmax is done in base-2: SCALE*log2(e) folded into Q load.
// ---------------------------------------------------------------------------
__global__ __launch_bounds__(256)
void attn_kernel(const float* __restrict__ qh, const float* __restrict__ kh,
                 const float* __restrict__ vh, float* __restrict__ attn_out,
                 float* __restrict__ xout, const int* __restrict__ umptr)
{
    extern __shared__ float smem[];
    float* sQ = smem;              // 64*65
    float* sK = sQ + 64 * 65;      // 64*65
    float* sV = sK + 64 * 65;      // 64*65
    float* sP = sV + 64 * 65;      // 64*65
    float* sM = sP + 64 * 65;      // 64
    float* sL = sM + 64;           // 64

    const int tid = threadIdx.x;
    const int qt  = blockIdx.x;
    const int bh  = blockIdx.y;
    const int um  = umptr[0];
    const int q0  = qt * 64;
    const int ty  = tid >> 4;
    const int tx  = tid & 15;
    const float SF = 0.125f * 1.4426950408889634f;  // HEAD_DIM^-0.5 * log2(e)

    const float* qb = qh + ((size_t)bh * SEQ + q0) * HDIM;
    const float* kb = kh + (size_t)bh * SEQ * HDIM;
    const float* vb = vh + (size_t)bh * SEQ * HDIM;
    float* ab = attn_out + (size_t)bh * SEQ * SEQ;

    // load Q tile (scaled, log2-domain)
#pragma unroll
    for (int l = 0; l < 4; ++l) {
        int id = tid + l * 256;
        int r = id >> 4, c = (id & 15) << 2;
        float4 v = *(const float4*)(qb + r * 64 + c);
        sQ[r * 65 + c + 0] = v.x * SF;
        sQ[r * 65 + c + 1] = v.y * SF;
        sQ[r * 65 + c + 2] = v.z * SF;
        sQ[r * 65 + c + 3] = v.w * SF;
    }
    if (tid < 64) { sM[tid] = -3.0e38f; sL[tid] = 0.0f; }
    __syncthreads();

    const int nkt = um ? (qt + 1) : (SEQ / 64);

    // ---------------- pass 1: row stats ----------------
    for (int kt = 0; kt < nkt; ++kt) {
#pragma unroll
        for (int l = 0; l < 4; ++l) {
            int id = tid + l * 256;
            int r = id >> 4, c = (id & 15) << 2;
            float4 v = *(const float4*)(kb + (size_t)(kt * 64 + r) * 64 + c);
            sK[r * 65 + c + 0] = v.x;
            sK[r * 65 + c + 1] = v.y;
            sK[r * 65 + c + 2] = v.z;
            sK[r * 65 + c + 3] = v.w;
        }
        __syncthreads();

        float acc[4][4];
#pragma unroll
        for (int i = 0; i < 4; ++i)
#pragma unroll
            for (int j = 0; j < 4; ++j) acc[i][j] = 0.0f;
#pragma unroll 8
        for (int d = 0; d < 64; ++d) {
            float a[4], b[4];
#pragma unroll
            for (int i = 0; i < 4; ++i) a[i] = sQ[(ty * 4 + i) * 65 + d];
#pragma unroll
            for (int j = 0; j < 4; ++j) b[j] = sK[(tx * 4 + j) * 65 + d];
#pragma unroll
            for (int i = 0; i < 4; ++i)
#pragma unroll
                for (int j = 0; j < 4; ++j)
                    acc[i][j] = fmaf(a[i], b[j], acc[i][j]);
        }
        if (um && kt == qt) {
#pragma unroll
            for (int i = 0; i < 4; ++i)
#pragma unroll
                for (int j = 0; j < 4; ++j)
                    if (tx * 4 + j > ty * 4 + i) acc[i][j] = -3.0e9f;
        }
#pragma unroll
        for (int i = 0; i < 4; ++i)
#pragma unroll
            for (int j = 0; j < 4; ++j)
                sP[(ty * 4 + i) * 65 + tx * 4 + j] = acc[i][j];
        __syncthreads();

        if (tid < 64) {
            const float* row = sP + tid * 65;
            float mo = sM[tid];
            float t = -3.0e38f;
#pragma unroll 8
            for (int c = 0; c < 64; ++c) t = fmaxf(t, row[c]);
            float mn = fmaxf(mo, t);
            float s = 0.0f;
#pragma unroll 8
            for (int c = 0; c < 64; ++c) s += exp2f(row[c] - mn);
            sL[tid] = sL[tid] * exp2f(mo - mn) + s;
            sM[tid] = mn;
        }
        __syncthreads();
    }

    if (tid < 64) sL[tid] = 1.0f / sL[tid];
    __syncthreads();

    // ---------------- pass 2: attn write + O accumulate ----------------
    float accO[4][4];
#pragma unroll
    for (int i = 0; i < 4; ++i)
#pragma unroll
        for (int j = 0; j < 4; ++j) accO[i][j] = 0.0f;

    for (int kt = 0; kt < nkt; ++kt) {
#pragma unroll
        for (int l = 0; l < 4; ++l) {
            int id = tid + l * 256;
            int r = id >> 4, c = (id & 15) << 2;
            float4 v = *(const float4*)(kb + (size_t)(kt * 64 + r) * 64 + c);
            sK[r * 65 + c + 0] = v.x;
            sK[r * 65 + c + 1] = v.y;
            sK[r * 65 + c + 2] = v.z;
            sK[r * 65 + c + 3] = v.w;
            float4 w = *(const float4*)(vb + (size_t)(kt * 64 + r) * 64 + c);
            sV[r * 65 + c + 0] = w.x;
            sV[r * 65 + c + 1] = w.y;
            sV[r * 65 + c + 2] = w.z;
            sV[r * 65 + c + 3] = w.w;
        }
        __syncthreads();

        float acc[4][4];
#pragma unroll
        for (int i = 0; i < 4; ++i)
#pragma unroll
            for (int j = 0; j < 4; ++j) acc[i][j] = 0.0f;
#pragma unroll 8
        for (int d = 0; d < 64; ++d) {
            float a[4], b[4];
#pragma unroll
            for (int i = 0; i < 4; ++i) a[i] = sQ[(ty * 4 + i) * 65 + d];
#pragma unroll
            for (int j = 0; j < 4; ++j) b[j] = sK[(tx * 4 + j) * 65 + d];
#pragma unroll
            for (int i = 0; i < 4; ++i)
#pragma unroll
                for (int j = 0; j < 4; ++j)
                    acc[i][j] = fmaf(a[i], b[j], acc[i][j]);
        }
        if (um && kt == qt) {
#pragma unroll
            for (int i = 0; i < 4; ++i)
#pragma unroll
                for (int j = 0; j < 4; ++j)
                    if (tx * 4 + j > ty * 4 + i) acc[i][j] = -3.0e9f;
        }
#pragma unroll
        for (int i = 0; i < 4; ++i) {
            int r = ty * 4 + i;
            float m = sM[r], il = sL[r];
            float4 p;
            p.x = exp2f(acc[i][0] - m) * il;
            p.y = exp2f(acc[i][1] - m) * il;
            p.z = exp2f(acc[i][2] - m) * il;
            p.w = exp2f(acc[i][3] - m) * il;
            *(float4*)(ab + (size_t)(q0 + r) * SEQ + kt * 64 + tx * 4) = p;
            sP[r * 65 + tx * 4 + 0] = p.x;
            sP[r * 65 + tx * 4 + 1] = p.y;
            sP[r * 65 + tx * 4 + 2] = p.z;
            sP[r * 65 + tx * 4 + 3] = p.w;
        }
        __syncthreads();

#pragma unroll 8
        for (int k = 0; k < 64; ++k) {
            float pa[4], vv[4];
#pragma unroll
            for (int i = 0; i < 4; ++i) pa[i] = sP[(ty * 4 + i) * 65 + k];
#pragma unroll
            for (int j = 0; j < 4; ++j) vv[j] = sV[k * 65 + tx * 4 + j];
#pragma unroll
            for (int i = 0; i < 4; ++i)
#pragma unroll
                for (int j = 0; j < 4; ++j)
                    accO[i][j] = fmaf(pa[i], vv[j], accO[i][j]);
        }
        __syncthreads();
    }

    // zero-fill fully-masked key region (exp underflow => exact zeros in ref)
    if (um && nkt < SEQ / 64) {
        int c0 = nkt * 64;
        int nf4 = (SEQ - c0) >> 2;
        float4 z = make_float4(0.f, 0.f, 0.f, 0.f);
        for (int idx = tid; idx < 64 * nf4; idx += 256) {
            int r = idx / nf4;
            int c = c0 + (idx % nf4) * 4;
            *(float4*)(ab + (size_t)(q0 + r) * SEQ + c) = z;
        }
    }

    // write O into [b][n][h*64+d] layout for the projection GEMM
    int b = bh >> 4, h = bh & 15;
#pragma unroll
    for (int i = 0; i < 4; ++i) {
        int r = q0 + ty * 4 + i;
        float4 v = make_float4(accO[i][0], accO[i][1], accO[i][2], accO[i][3]);
        *(float4*)(xout + ((size_t)b * SEQ + r) * DIMC + h * 64 + tx * 4) = v;
    }
}

// ---------------------------------------------------------------------------
extern "C" void kernel_launch(void* const* d_in, const int* in_sizes, int n_in,
                              void* d_out, int out_size)
{
    const float* q      = (const float*)d_in[0];
    const float* k      = (const float*)d_in[1];
    const float* v      = (const float*)d_in[2];
    const float* qkv_w  = (const float*)d_in[3];
    const float* proj_w = (const float*)d_in[4];
    const float* proj_b = (const float*)d_in[5];
    const int*   um     = (const int*)d_in[6];

    float* out      = (float*)d_out;                         // x: [B,N,C]
    float* attn_out = out + (size_t)MROWS * DIMC;            // attn: [B,H,N,N]

    float *qh, *kh, *vh, *xb;
    cudaGetSymbolAddress((void**)&qh, g_qh);
    cudaGetSymbolAddress((void**)&kh, g_kh);
    cudaGetSymbolAddress((void**)&vh, g_vh);
    cudaGetSymbolAddress((void**)&xb, g_x);

    dim3 ggrid(DIMC / 128, MROWS / 128);   // (8, 32)
    gemm_nt<<<ggrid, 256>>>(q, qkv_w,                        nullptr, qh, 1);
    gemm_nt<<<ggrid, 256>>>(k, qkv_w + (size_t)DIMC * DIMC,  nullptr, kh, 1);
    gemm_nt<<<ggrid, 256>>>(v, qkv_w + (size_t)2 * DIMC * DIMC, nullptr, vh, 1);

    const int ATTN_SMEM = (4 * 64 * 65 + 128) * (int)sizeof(float);  // 67072 B
    cudaFuncSetAttribute(attn_kernel, cudaFuncAttributeMaxDynamicSharedMemorySize, ATTN_SMEM);
    attn_kernel<<<dim3(SEQ / 64, BATCH * NHEAD), 256, ATTN_SMEM>>>(qh, kh, vh, attn_out, xb, um);

    gemm_nt<<<ggrid, 256>>>(xb, proj_w, proj_b, out, 0);
}